// round 1
// baseline (speedup 1.0000x reference)
#include <cuda_runtime.h>
#include <math.h>

#define CCH 512
#define HWT 4096
#define BATCH 2
#define NGROUPS 32
#define CPG 16

// ---------------- scratch (allocation-free) ----------------
__device__ float g_h[(size_t)BATCH * CCH * HWT];   // normalized, (B, C, HW)
__device__ float g_q[(size_t)BATCH * HWT * CCH];   // (B, HW, C)
__device__ float g_k[(size_t)BATCH * HWT * CCH];
__device__ float g_v[(size_t)BATCH * HWT * CCH];
__device__ float g_o[(size_t)BATCH * HWT * CCH];   // attn output (B, HW, C)
__device__ float g_s[(size_t)BATCH * HWT * HWT];   // scores (B, HW, HW)

// ---------------- GroupNorm ----------------
// one block per (batch, group); x layout (B, C, HW); writes h same layout
__global__ void gn_kernel(const float* __restrict__ x,
                          const float* __restrict__ gw,
                          const float* __restrict__ gb,
                          float* __restrict__ h) {
    const int bg = blockIdx.x;              // 0..63
    const int g  = bg & (NGROUPS - 1);
    const size_t base = (size_t)bg * CPG * HWT;
    const float4* xp = (const float4*)(x + base);
    float4* hp = (float4*)(h + base);
    const int N4 = CPG * HWT / 4;           // 16384

    float s = 0.f, ss = 0.f;
    for (int i = threadIdx.x; i < N4; i += blockDim.x) {
        float4 v = xp[i];
        s  += v.x + v.y + v.z + v.w;
        ss += v.x * v.x + v.y * v.y + v.z * v.z + v.w * v.w;
    }
    __shared__ float rs[32], rss[32];
    #pragma unroll
    for (int o = 16; o > 0; o >>= 1) {
        s  += __shfl_xor_sync(~0u, s,  o);
        ss += __shfl_xor_sync(~0u, ss, o);
    }
    const int wid = threadIdx.x >> 5, lid = threadIdx.x & 31;
    if (lid == 0) { rs[wid] = s; rss[wid] = ss; }
    __syncthreads();
    if (threadIdx.x == 0) {
        const int nw = blockDim.x >> 5;
        float ts = 0.f, tss = 0.f;
        for (int i = 0; i < nw; i++) { ts += rs[i]; tss += rss[i]; }
        rs[0] = ts; rss[0] = tss;
    }
    __syncthreads();
    const float invN = 1.f / (float)(CPG * HWT);
    const float mean = rs[0] * invN;
    const float var  = fmaxf(rss[0] * invN - mean * mean, 0.f);
    const float inv  = rsqrtf(var + 1e-6f);

    for (int i = threadIdx.x; i < N4; i += blockDim.x) {
        const int c = g * CPG + (i >> 10);  // i*4 / 4096
        const float a  = inv * gw[c];
        const float bo = gb[c] - mean * a;
        float4 v = xp[i];
        v.x = v.x * a + bo; v.y = v.y * a + bo;
        v.z = v.z * a + bo; v.w = v.w * a + bo;
        hp[i] = v;
    }
}

// ---------------- generic batched SGEMM ----------------
// out[m][n] = scale * sum_k A(k,m) * B(k,n)  (+bias)(+res)
// A_KMAJOR: A stored A[k*lda + m], else A[m*lda + k]
// B_NMAJOR: B stored B[k*ldb + n], else B[n*ldb + k]
// BIAS_MODE: 0 none, 1 per-n, 2 per-m.  HAS_RES adds res (same layout as out).
template<bool A_KMAJOR, bool B_NMAJOR, int BIAS_MODE, bool HAS_RES>
__global__ __launch_bounds__(256)
void gemm_kernel(const float* __restrict__ A, const float* __restrict__ B,
                 const float* __restrict__ bias, const float* __restrict__ res,
                 float* __restrict__ out,
                 int M, int N, int K, int lda, int ldb, int ldo, float scale,
                 size_t sA, size_t sB, size_t sO, size_t sR) {
    constexpr int BM = 128, BN = 128, BK = 8, TM = 8, TN = 8;
    __shared__ float As[BK][BM];
    __shared__ float Bs[BK][BN];

    const int bz = blockIdx.z;
    A += (size_t)bz * sA;
    B += (size_t)bz * sB;
    out += (size_t)bz * sO;
    if (HAS_RES) res += (size_t)bz * sR;

    const int m0 = blockIdx.y * BM;
    const int n0 = blockIdx.x * BN;
    const int tid = threadIdx.x;
    const int tx = tid & 15, ty = tid >> 4;

    float acc[TM][TN];
    #pragma unroll
    for (int i = 0; i < TM; i++)
        #pragma unroll
        for (int j = 0; j < TN; j++) acc[i][j] = 0.f;

    for (int kt = 0; kt < K; kt += BK) {
        if (A_KMAJOR) {
            const int k = tid >> 5, m = (tid & 31) << 2;
            float4 v = *(const float4*)&A[(size_t)(kt + k) * lda + m0 + m];
            *(float4*)&As[k][m] = v;
        } else {
            const int m = tid >> 1, kq = (tid & 1) << 2;
            float4 v = *(const float4*)&A[(size_t)(m0 + m) * lda + kt + kq];
            As[kq + 0][m] = v.x; As[kq + 1][m] = v.y;
            As[kq + 2][m] = v.z; As[kq + 3][m] = v.w;
        }
        if (B_NMAJOR) {
            const int k = tid >> 5, n = (tid & 31) << 2;
            float4 v = *(const float4*)&B[(size_t)(kt + k) * ldb + n0 + n];
            *(float4*)&Bs[k][n] = v;
        } else {
            const int n = tid >> 1, kq = (tid & 1) << 2;
            float4 v = *(const float4*)&B[(size_t)(n0 + n) * ldb + kt + kq];
            Bs[kq + 0][n] = v.x; Bs[kq + 1][n] = v.y;
            Bs[kq + 2][n] = v.z; Bs[kq + 3][n] = v.w;
        }
        __syncthreads();
        #pragma unroll
        for (int k = 0; k < BK; k++) {
            float ra[TM], rb[TN];
            *(float4*)&ra[0] = *(const float4*)&As[k][ty * TM];
            *(float4*)&ra[4] = *(const float4*)&As[k][ty * TM + 4];
            *(float4*)&rb[0] = *(const float4*)&Bs[k][tx * TN];
            *(float4*)&rb[4] = *(const float4*)&Bs[k][tx * TN + 4];
            #pragma unroll
            for (int i = 0; i < TM; i++)
                #pragma unroll
                for (int j = 0; j < TN; j++)
                    acc[i][j] += ra[i] * rb[j];
        }
        __syncthreads();
    }

    #pragma unroll
    for (int i = 0; i < TM; i++) {
        const int m = m0 + ty * TM + i;
        const size_t rowo = (size_t)m * ldo;
        const float bm = (BIAS_MODE == 2) ? bias[m] : 0.f;
        #pragma unroll
        for (int jj = 0; jj < TN; jj += 4) {
            const int n = n0 + tx * TN + jj;
            float4 v;
            v.x = acc[i][jj + 0] * scale;
            v.y = acc[i][jj + 1] * scale;
            v.z = acc[i][jj + 2] * scale;
            v.w = acc[i][jj + 3] * scale;
            if (BIAS_MODE == 1) {
                float4 bn = *(const float4*)&bias[n];
                v.x += bn.x; v.y += bn.y; v.z += bn.z; v.w += bn.w;
            } else if (BIAS_MODE == 2) {
                v.x += bm; v.y += bm; v.z += bm; v.w += bm;
            }
            if (HAS_RES) {
                float4 r = *(const float4*)&res[rowo + n];
                v.x += r.x; v.y += r.y; v.z += r.z; v.w += r.w;
            }
            *(float4*)&out[rowo + n] = v;
        }
    }
}

// ---------------- row softmax (in place), one block per row ----------------
__global__ __launch_bounds__(256)
void softmax_kernel(float* __restrict__ s) {
    const size_t row = blockIdx.x;
    float4* p4 = (float4*)(s + row * HWT);
    __shared__ float buf[HWT];
    __shared__ float red[32];
    float4* b4 = (float4*)buf;
    const int tid = threadIdx.x;
    const int wid = tid >> 5, lid = tid & 31;

    float mx = -1e30f;
    for (int i = tid; i < HWT / 4; i += 256) {
        float4 v = p4[i];
        b4[i] = v;
        mx = fmaxf(mx, fmaxf(fmaxf(v.x, v.y), fmaxf(v.z, v.w)));
    }
    #pragma unroll
    for (int o = 16; o > 0; o >>= 1) mx = fmaxf(mx, __shfl_xor_sync(~0u, mx, o));
    if (lid == 0) red[wid] = mx;
    __syncthreads();
    if (tid == 0) {
        float m2 = red[0];
        for (int i = 1; i < 8; i++) m2 = fmaxf(m2, red[i]);
        red[0] = m2;
    }
    __syncthreads();
    const float rowmax = red[0];
    __syncthreads();

    float sum = 0.f;
    for (int i = tid; i < HWT / 4; i += 256) {
        float4 v = b4[i];
        v.x = __expf(v.x - rowmax); v.y = __expf(v.y - rowmax);
        v.z = __expf(v.z - rowmax); v.w = __expf(v.w - rowmax);
        sum += v.x + v.y + v.z + v.w;
        b4[i] = v;
    }
    #pragma unroll
    for (int o = 16; o > 0; o >>= 1) sum += __shfl_xor_sync(~0u, sum, o);
    if (lid == 0) red[wid] = sum;
    __syncthreads();
    if (tid == 0) {
        float t = 0.f;
        for (int i = 0; i < 8; i++) t += red[i];
        red[0] = t;
    }
    __syncthreads();
    const float inv = 1.f / red[0];
    for (int i = tid; i < HWT / 4; i += 256) {
        float4 v = b4[i];
        v.x *= inv; v.y *= inv; v.z *= inv; v.w *= inv;
        p4[i] = v;
    }
}

// ---------------- launch ----------------
extern "C" void kernel_launch(void* const* d_in, const int* in_sizes, int n_in,
                              void* d_out, int out_size) {
    const float* x    = (const float*)d_in[0];
    const float* gn_w = (const float*)d_in[1];
    const float* gn_b = (const float*)d_in[2];
    const float* q_w  = (const float*)d_in[3];
    const float* q_b  = (const float*)d_in[4];
    const float* k_w  = (const float*)d_in[5];
    const float* k_b  = (const float*)d_in[6];
    const float* v_w  = (const float*)d_in[7];
    const float* v_b  = (const float*)d_in[8];
    const float* p_w  = (const float*)d_in[9];
    const float* p_b  = (const float*)d_in[10];
    float* out = (float*)d_out;

    float *h, *q, *k, *v, *o, *s;
    cudaGetSymbolAddress((void**)&h, g_h);
    cudaGetSymbolAddress((void**)&q, g_q);
    cudaGetSymbolAddress((void**)&k, g_k);
    cudaGetSymbolAddress((void**)&v, g_v);
    cudaGetSymbolAddress((void**)&o, g_o);
    cudaGetSymbolAddress((void**)&s, g_s);

    const size_t TOK = (size_t)HWT * CCH;      // 4096*512
    const size_t SS  = (size_t)HWT * HWT;      // 4096*4096
    const float att_scale = 0.04419417382415922f; // 1/sqrt(512)

    // 1. GroupNorm -> h (B, C, HW)
    gn_kernel<<<BATCH * NGROUPS, 512>>>(x, gn_w, gn_b, h);

    // 2. q/k/v = h^T @ W^T + b : M=4096 tokens, N=512, K=512
    dim3 gq(CCH / 128, HWT / 128, BATCH);
    gemm_kernel<true, false, 1, false><<<gq, 256>>>(h, q_w, q_b, nullptr, q,
        HWT, CCH, CCH, HWT, CCH, CCH, 1.f, TOK, 0, TOK, 0);
    gemm_kernel<true, false, 1, false><<<gq, 256>>>(h, k_w, k_b, nullptr, k,
        HWT, CCH, CCH, HWT, CCH, CCH, 1.f, TOK, 0, TOK, 0);
    gemm_kernel<true, false, 1, false><<<gq, 256>>>(h, v_w, v_b, nullptr, v,
        HWT, CCH, CCH, HWT, CCH, CCH, 1.f, TOK, 0, TOK, 0);

    // 3. scores = scale * Q @ K^T : M=N=4096, K=512
    dim3 gs(HWT / 128, HWT / 128, BATCH);
    gemm_kernel<false, false, 0, false><<<gs, 256>>>(q, k, nullptr, nullptr, s,
        HWT, HWT, CCH, CCH, CCH, HWT, att_scale, TOK, TOK, SS, 0);

    // 4. softmax rows
    softmax_kernel<<<BATCH * HWT, 256>>>(s);

    // 5. o = attn @ V : M=4096, N=512, K=4096
    dim3 ga(CCH / 128, HWT / 128, BATCH);
    gemm_kernel<false, true, 0, false><<<ga, 256>>>(s, v, nullptr, nullptr, o,
        HWT, CCH, HWT, HWT, CCH, CCH, 1.f, SS, TOK, TOK, 0);

    // 6. out = x + o @ P^T + p_b, computed channel-major:
    //    M=512 channels, N=4096 tokens, K=512; output lands in (B,C,H,W)
    dim3 gp(HWT / 128, CCH / 128, BATCH);
    gemm_kernel<false, false, 2, true><<<gp, 256>>>(p_w, o, p_b, x, out,
        CCH, HWT, CCH, CCH, CCH, HWT, 1.f, 0, TOK, (size_t)CCH * HWT, (size_t)CCH * HWT);
}

// round 2
// speedup vs baseline: 2.0680x; 2.0680x over previous
#include <cuda_runtime.h>
#include <math.h>
#include <stdint.h>

#define CCH 512
#define HWT 4096
#define BATCH 2
#define NGROUPS 32
#define CPG 16

// ---------------- scratch (allocation-free) ----------------
__device__ float g_h[(size_t)BATCH * CCH * HWT];   // normalized, (B, C, HW)
__device__ float g_q[(size_t)BATCH * HWT * CCH];   // (B, HW, C)
__device__ float g_k[(size_t)BATCH * HWT * CCH];
__device__ float g_v[(size_t)BATCH * HWT * CCH];
__device__ float g_o[(size_t)BATCH * HWT * CCH];   // attn output (B, HW, C)
__device__ float g_s[(size_t)BATCH * HWT * HWT];   // scores (B, HW, HW)

// ---------------- helpers ----------------
__device__ __forceinline__ uint32_t f2tf32(float f) {
    uint32_t r;
    asm("cvt.rna.tf32.f32 %0, %1;" : "=r"(r) : "f"(f));
    return r;
}

__device__ __forceinline__ void mma_tf32(float* c, const uint32_t* a, const uint32_t* b) {
    asm("mma.sync.aligned.m16n8k8.row.col.f32.tf32.tf32.f32 "
        "{%0,%1,%2,%3}, {%4,%5,%6,%7}, {%8,%9}, {%0,%1,%2,%3};"
        : "+f"(c[0]), "+f"(c[1]), "+f"(c[2]), "+f"(c[3])
        : "r"(a[0]), "r"(a[1]), "r"(a[2]), "r"(a[3]), "r"(b[0]), "r"(b[1]));
}

// ---------------- GroupNorm ----------------
__global__ void gn_kernel(const float* __restrict__ x,
                          const float* __restrict__ gw,
                          const float* __restrict__ gb,
                          float* __restrict__ h) {
    const int bg = blockIdx.x;              // 0..63
    const int g  = bg & (NGROUPS - 1);
    const size_t base = (size_t)bg * CPG * HWT;
    const float4* xp = (const float4*)(x + base);
    float4* hp = (float4*)(h + base);
    const int N4 = CPG * HWT / 4;           // 16384

    float s = 0.f, ss = 0.f;
    for (int i = threadIdx.x; i < N4; i += blockDim.x) {
        float4 v = xp[i];
        s  += v.x + v.y + v.z + v.w;
        ss += v.x * v.x + v.y * v.y + v.z * v.z + v.w * v.w;
    }
    __shared__ float rs[32], rss[32];
    #pragma unroll
    for (int o = 16; o > 0; o >>= 1) {
        s  += __shfl_xor_sync(~0u, s,  o);
        ss += __shfl_xor_sync(~0u, ss, o);
    }
    const int wid = threadIdx.x >> 5, lid = threadIdx.x & 31;
    if (lid == 0) { rs[wid] = s; rss[wid] = ss; }
    __syncthreads();
    if (threadIdx.x == 0) {
        const int nw = blockDim.x >> 5;
        float ts = 0.f, tss = 0.f;
        for (int i = 0; i < nw; i++) { ts += rs[i]; tss += rss[i]; }
        rs[0] = ts; rss[0] = tss;
    }
    __syncthreads();
    const float invN = 1.f / (float)(CPG * HWT);
    const float mean = rs[0] * invN;
    const float var  = fmaxf(rss[0] * invN - mean * mean, 0.f);
    const float inv  = rsqrtf(var + 1e-6f);

    for (int i = threadIdx.x; i < N4; i += blockDim.x) {
        const int c = g * CPG + (i >> 10);
        const float a  = inv * gw[c];
        const float bo = gb[c] - mean * a;
        float4 v = xp[i];
        v.x = v.x * a + bo; v.y = v.y * a + bo;
        v.z = v.z * a + bo; v.w = v.w * a + bo;
        hp[i] = v;
    }
}

// ---------------- tf32 tensor-core GEMM ----------------
// out[m][n] = scale * sum_k A(m,k)*B(n,k) (+bias)(+res)
// A_KM: A stored A[k*lda+m] (k-major rows); else A[m*lda+k]
// B_KM: B stored B[k*ldb+n]; else B[n*ldb+k]
// BIAS: 0 none, 1 per-n, 2 per-m.  RES adds res[m*ldo+n].
template<bool A_KM, bool B_KM, int BIAS, bool RES>
__global__ __launch_bounds__(256, 2)
void mma_gemm(const float* __restrict__ A, const float* __restrict__ B,
              const float* __restrict__ bias, const float* __restrict__ res,
              float* __restrict__ out,
              int lda, int ldb, int ldo, int K, float scale,
              size_t sA, size_t sB, size_t sO, size_t sR) {
    constexpr int BK = 32;
    __shared__ uint32_t As[BK][132];
    __shared__ uint32_t Bs[BK][132];

    const int bz = blockIdx.z;
    A += (size_t)bz * sA;
    B += (size_t)bz * sB;
    out += (size_t)bz * sO;
    if (RES) res += (size_t)bz * sR;

    const int m0 = blockIdx.y * 128;
    const int n0 = blockIdx.x * 128;
    const int tid = threadIdx.x;
    const int lane = tid & 31;
    const int wid = tid >> 5;
    const int wm = wid & 1;     // 0..1 -> 64 rows
    const int wn = wid >> 1;    // 0..3 -> 32 cols

    float acc[4][4][4];
    #pragma unroll
    for (int mi = 0; mi < 4; mi++)
        #pragma unroll
        for (int ni = 0; ni < 4; ni++)
            #pragma unroll
            for (int r = 0; r < 4; r++) acc[mi][ni][r] = 0.f;

    for (int kt = 0; kt < K; kt += BK) {
        // ---- load A tile into As[k][m] ----
        float4 va[4], vb[4];
        if (A_KM) {
            const int k = tid >> 3;
            #pragma unroll
            for (int it = 0; it < 4; it++) {
                const int mq = (tid & 7) + 8 * it;
                va[it] = *(const float4*)&A[(size_t)(kt + k) * lda + m0 + mq * 4];
            }
        } else {
            #pragma unroll
            for (int it = 0; it < 4; it++) {
                const int idx = tid + 256 * it;
                const int m = idx >> 3, kq = idx & 7;
                va[it] = *(const float4*)&A[(size_t)(m0 + m) * lda + kt + kq * 4];
            }
        }
        if (B_KM) {
            const int k = tid >> 3;
            #pragma unroll
            for (int it = 0; it < 4; it++) {
                const int nq = (tid & 7) + 8 * it;
                vb[it] = *(const float4*)&B[(size_t)(kt + k) * ldb + n0 + nq * 4];
            }
        } else {
            #pragma unroll
            for (int it = 0; it < 4; it++) {
                const int idx = tid + 256 * it;
                const int n = idx >> 3, kq = idx & 7;
                vb[it] = *(const float4*)&B[(size_t)(n0 + n) * ldb + kt + kq * 4];
            }
        }
        __syncthreads();
        if (A_KM) {
            const int k = tid >> 3;
            #pragma unroll
            for (int it = 0; it < 4; it++) {
                const int m = ((tid & 7) + 8 * it) * 4;
                As[k][m + 0] = f2tf32(va[it].x); As[k][m + 1] = f2tf32(va[it].y);
                As[k][m + 2] = f2tf32(va[it].z); As[k][m + 3] = f2tf32(va[it].w);
            }
        } else {
            #pragma unroll
            for (int it = 0; it < 4; it++) {
                const int idx = tid + 256 * it;
                const int m = idx >> 3, kq = (idx & 7) * 4;
                As[kq + 0][m] = f2tf32(va[it].x); As[kq + 1][m] = f2tf32(va[it].y);
                As[kq + 2][m] = f2tf32(va[it].z); As[kq + 3][m] = f2tf32(va[it].w);
            }
        }
        if (B_KM) {
            const int k = tid >> 3;
            #pragma unroll
            for (int it = 0; it < 4; it++) {
                const int n = ((tid & 7) + 8 * it) * 4;
                Bs[k][n + 0] = f2tf32(vb[it].x); Bs[k][n + 1] = f2tf32(vb[it].y);
                Bs[k][n + 2] = f2tf32(vb[it].z); Bs[k][n + 3] = f2tf32(vb[it].w);
            }
        } else {
            #pragma unroll
            for (int it = 0; it < 4; it++) {
                const int idx = tid + 256 * it;
                const int n = idx >> 3, kq = (idx & 7) * 4;
                Bs[kq + 0][n] = f2tf32(vb[it].x); Bs[kq + 1][n] = f2tf32(vb[it].y);
                Bs[kq + 2][n] = f2tf32(vb[it].z); Bs[kq + 3][n] = f2tf32(vb[it].w);
            }
        }
        __syncthreads();

        // ---- compute ----
        #pragma unroll
        for (int kk = 0; kk < BK; kk += 8) {
            uint32_t af[4][4], bf[4][2];
            #pragma unroll
            for (int mi = 0; mi < 4; mi++) {
                const int r = wm * 64 + mi * 16 + (lane >> 2);
                const int c = kk + (lane & 3);
                af[mi][0] = As[c][r];     af[mi][1] = As[c][r + 8];
                af[mi][2] = As[c + 4][r]; af[mi][3] = As[c + 4][r + 8];
            }
            #pragma unroll
            for (int ni = 0; ni < 4; ni++) {
                const int n = wn * 32 + ni * 8 + (lane >> 2);
                bf[ni][0] = Bs[kk + (lane & 3)][n];
                bf[ni][1] = Bs[kk + 4 + (lane & 3)][n];
            }
            #pragma unroll
            for (int mi = 0; mi < 4; mi++)
                #pragma unroll
                for (int ni = 0; ni < 4; ni++)
                    mma_tf32(acc[mi][ni], af[mi], bf[ni]);
        }
        __syncthreads();
    }

    // ---- epilogue ----
    #pragma unroll
    for (int mi = 0; mi < 4; mi++) {
        const int r0 = m0 + wm * 64 + mi * 16 + (lane >> 2);
        #pragma unroll
        for (int ni = 0; ni < 4; ni++) {
            const int cc = n0 + wn * 32 + ni * 8 + 2 * (lane & 3);
            #pragma unroll
            for (int half = 0; half < 2; half++) {
                const int r = r0 + half * 8;
                float2 v;
                v.x = acc[mi][ni][half * 2 + 0] * scale;
                v.y = acc[mi][ni][half * 2 + 1] * scale;
                if (BIAS == 1) { v.x += bias[cc]; v.y += bias[cc + 1]; }
                else if (BIAS == 2) { const float bm = bias[r]; v.x += bm; v.y += bm; }
                if (RES) {
                    float2 rr = *(const float2*)&res[(size_t)r * ldo + cc];
                    v.x += rr.x; v.y += rr.y;
                }
                *(float2*)&out[(size_t)r * ldo + cc] = v;
            }
        }
    }
}

// ---------------- row softmax (in place), one block per row ----------------
__global__ __launch_bounds__(256)
void softmax_kernel(float* __restrict__ s) {
    const size_t row = blockIdx.x;
    float4* p4 = (float4*)(s + row * HWT);
    __shared__ float buf[HWT];
    __shared__ float red[32];
    float4* b4 = (float4*)buf;
    const int tid = threadIdx.x;
    const int wid = tid >> 5, lid = tid & 31;

    float mx = -1e30f;
    for (int i = tid; i < HWT / 4; i += 256) {
        float4 v = p4[i];
        b4[i] = v;
        mx = fmaxf(mx, fmaxf(fmaxf(v.x, v.y), fmaxf(v.z, v.w)));
    }
    #pragma unroll
    for (int o = 16; o > 0; o >>= 1) mx = fmaxf(mx, __shfl_xor_sync(~0u, mx, o));
    if (lid == 0) red[wid] = mx;
    __syncthreads();
    if (tid == 0) {
        float m2 = red[0];
        for (int i = 1; i < 8; i++) m2 = fmaxf(m2, red[i]);
        red[0] = m2;
    }
    __syncthreads();
    const float rowmax = red[0];
    __syncthreads();

    float sum = 0.f;
    for (int i = tid; i < HWT / 4; i += 256) {
        float4 v = b4[i];
        v.x = __expf(v.x - rowmax); v.y = __expf(v.y - rowmax);
        v.z = __expf(v.z - rowmax); v.w = __expf(v.w - rowmax);
        sum += v.x + v.y + v.z + v.w;
        b4[i] = v;
    }
    #pragma unroll
    for (int o = 16; o > 0; o >>= 1) sum += __shfl_xor_sync(~0u, sum, o);
    if (lid == 0) red[wid] = sum;
    __syncthreads();
    if (tid == 0) {
        float t = 0.f;
        for (int i = 0; i < 8; i++) t += red[i];
        red[0] = t;
    }
    __syncthreads();
    const float inv = 1.f / red[0];
    for (int i = tid; i < HWT / 4; i += 256) {
        float4 v = b4[i];
        v.x *= inv; v.y *= inv; v.z *= inv; v.w *= inv;
        p4[i] = v;
    }
}

// ---------------- launch ----------------
extern "C" void kernel_launch(void* const* d_in, const int* in_sizes, int n_in,
                              void* d_out, int out_size) {
    const float* x    = (const float*)d_in[0];
    const float* gn_w = (const float*)d_in[1];
    const float* gn_b = (const float*)d_in[2];
    const float* q_w  = (const float*)d_in[3];
    const float* q_b  = (const float*)d_in[4];
    const float* k_w  = (const float*)d_in[5];
    const float* k_b  = (const float*)d_in[6];
    const float* v_w  = (const float*)d_in[7];
    const float* v_b  = (const float*)d_in[8];
    const float* p_w  = (const float*)d_in[9];
    const float* p_b  = (const float*)d_in[10];
    float* out = (float*)d_out;

    float *h, *q, *k, *v, *o, *s;
    cudaGetSymbolAddress((void**)&h, g_h);
    cudaGetSymbolAddress((void**)&q, g_q);
    cudaGetSymbolAddress((void**)&k, g_k);
    cudaGetSymbolAddress((void**)&v, g_v);
    cudaGetSymbolAddress((void**)&o, g_o);
    cudaGetSymbolAddress((void**)&s, g_s);

    const size_t TOK = (size_t)HWT * CCH;
    const size_t SS  = (size_t)HWT * HWT;
    const float att_scale = 0.04419417382415922f; // 1/sqrt(512)

    // 1. GroupNorm -> h (B, C, HW)
    gn_kernel<<<BATCH * NGROUPS, 512>>>(x, gn_w, gn_b, h);

    // 2. q/k/v: out[token][c] = sum_cin h[cin][token] * W[c][cin] + b[c]
    //    A = h (K-major, lda=HWT), B = W (n-major, ldb=CCH)
    dim3 gq(CCH / 128, HWT / 128, BATCH);
    mma_gemm<true, false, 1, false><<<gq, 256>>>(h, q_w, q_b, nullptr, q,
        HWT, CCH, CCH, CCH, 1.f, TOK, 0, TOK, 0);
    mma_gemm<true, false, 1, false><<<gq, 256>>>(h, k_w, k_b, nullptr, k,
        HWT, CCH, CCH, CCH, 1.f, TOK, 0, TOK, 0);
    mma_gemm<true, false, 1, false><<<gq, 256>>>(h, v_w, v_b, nullptr, v,
        HWT, CCH, CCH, CCH, 1.f, TOK, 0, TOK, 0);

    // 3. scores = scale * Q @ K^T
    dim3 gs(HWT / 128, HWT / 128, BATCH);
    mma_gemm<false, false, 0, false><<<gs, 256>>>(q, k, nullptr, nullptr, s,
        CCH, CCH, HWT, CCH, att_scale, TOK, TOK, SS, 0);

    // 4. softmax rows
    softmax_kernel<<<BATCH * HWT, 256>>>(s);

    // 5. o = attn @ V : A = s m-major (lda=HWT), B = v k-major (ldb=CCH)
    dim3 ga(CCH / 128, HWT / 128, BATCH);
    mma_gemm<false, true, 0, false><<<ga, 256>>>(s, v, nullptr, nullptr, o,
        HWT, CCH, CCH, HWT, 1.f, SS, TOK, TOK, 0);

    // 6. out = x + P @ o^T (channel-major): A = p_w (m-major), B = o (n-major)
    dim3 gp(HWT / 128, CCH / 128, BATCH);
    mma_gemm<false, false, 2, true><<<gp, 256>>>(p_w, o, p_b, x, out,
        CCH, CCH, HWT, CCH, 1.f, 0, TOK, (size_t)CCH * HWT, (size_t)CCH * HWT);
}

// round 4
// speedup vs baseline: 4.1973x; 2.0296x over previous
#include <cuda_runtime.h>
#include <math.h>
#include <stdint.h>

#define CCH 512
#define HWT 4096
#define BATCH 2
#define NGROUPS 32
#define CPG 16

// ---------------- scratch (allocation-free) ----------------
__device__ float  g_h[(size_t)BATCH * HWT * CCH];   // normalized, token-major (B, HW, C)
__device__ float  g_q[(size_t)BATCH * HWT * CCH];   // (B, HW, C)
__device__ float  g_k[(size_t)BATCH * HWT * CCH];
__device__ float  g_v[(size_t)BATCH * CCH * HWT];   // channel-major (B, C, HW)
__device__ float  g_o[(size_t)BATCH * HWT * CCH];   // attn out, token-major
__device__ float  g_s[(size_t)BATCH * HWT * HWT];   // scores
__device__ float2 g_stats[BATCH * NGROUPS];         // {mean, inv_std}

// ---------------- helpers ----------------
__device__ __forceinline__ uint32_t smem_u32(const void* p) {
    uint32_t a;
    asm("{ .reg .u64 t; cvta.to.shared.u64 t, %1; cvt.u32.u64 %0, t; }" : "=r"(a) : "l"(p));
    return a;
}
__device__ __forceinline__ void ldsm_x4(uint32_t& r0, uint32_t& r1, uint32_t& r2, uint32_t& r3,
                                        uint32_t addr) {
    asm volatile("ldmatrix.sync.aligned.m8n8.x4.shared.b16 {%0,%1,%2,%3}, [%4];"
                 : "=r"(r0), "=r"(r1), "=r"(r2), "=r"(r3) : "r"(addr));
}
__device__ __forceinline__ void mma_tf32(float* c, const uint32_t* a, const uint32_t* b) {
    asm("mma.sync.aligned.m16n8k8.row.col.f32.tf32.tf32.f32 "
        "{%0,%1,%2,%3}, {%4,%5,%6,%7}, {%8,%9}, {%0,%1,%2,%3};"
        : "+f"(c[0]), "+f"(c[1]), "+f"(c[2]), "+f"(c[3])
        : "r"(a[0]), "r"(a[1]), "r"(a[2]), "r"(a[3]), "r"(b[0]), "r"(b[1]));
}

// ---------------- GroupNorm stats ----------------
__global__ void gn_stats(const float* __restrict__ x, float2* __restrict__ st) {
    const int bg = blockIdx.x;
    const size_t base = (size_t)bg * CPG * HWT;
    const float4* xp = (const float4*)(x + base);
    const int N4 = CPG * HWT / 4;

    float s = 0.f, ss = 0.f;
    for (int i = threadIdx.x; i < N4; i += blockDim.x) {
        float4 v = xp[i];
        s  += v.x + v.y + v.z + v.w;
        ss += v.x * v.x + v.y * v.y + v.z * v.z + v.w * v.w;
    }
    __shared__ float rs[32], rss[32];
    #pragma unroll
    for (int o = 16; o > 0; o >>= 1) {
        s  += __shfl_xor_sync(~0u, s,  o);
        ss += __shfl_xor_sync(~0u, ss, o);
    }
    const int wid = threadIdx.x >> 5, lid = threadIdx.x & 31;
    if (lid == 0) { rs[wid] = s; rss[wid] = ss; }
    __syncthreads();
    if (threadIdx.x == 0) {
        const int nw = blockDim.x >> 5;
        float ts = 0.f, tss = 0.f;
        for (int i = 0; i < nw; i++) { ts += rs[i]; tss += rss[i]; }
        const float invN = 1.f / (float)(CPG * HWT);
        const float mean = ts * invN;
        const float var  = fmaxf(tss * invN - mean * mean, 0.f);
        st[bg] = make_float2(mean, rsqrtf(var + 1e-6f));
    }
}

// ---------------- GN apply + transpose -> token-major h ----------------
__global__ void gn_apply_t(const float* __restrict__ x,
                           const float* __restrict__ gw, const float* __restrict__ gb,
                           const float2* __restrict__ st, float* __restrict__ ht) {
    __shared__ float tile[32][33];
    const int b = blockIdx.z;
    const int c0 = blockIdx.y * 32, t0 = blockIdx.x * 32;
    const float* xp = x + (size_t)b * CCH * HWT;
    float* hp = ht + (size_t)b * HWT * CCH;

    #pragma unroll
    for (int j = threadIdx.y; j < 32; j += 8)
        tile[j][threadIdx.x] = xp[(size_t)(c0 + j) * HWT + t0 + threadIdx.x];
    __syncthreads();

    const int c = c0 + threadIdx.x;
    const float2 mv = st[b * NGROUPS + (c >> 4)];
    const float a  = mv.y * gw[c];
    const float bo = gb[c] - mv.x * a;
    #pragma unroll
    for (int j = threadIdx.y; j < 32; j += 8)
        hp[(size_t)(t0 + j) * CCH + c] = tile[threadIdx.x][j] * a + bo;
}

// ---------------- tf32 HMMA GEMM (ldmatrix + cp.async double buffer) ----------------
// out[m][n] = scale * sum_k A[m][k]*B[n][k] (+bias)(+res); A,B k-contiguous.
// BIAS: 0 none, 1 per-n, 2 per-m.  RES adds res[m*ldo+n].
template<int BIAS, bool RES>
__global__ __launch_bounds__(256, 2)
void mma_gemm(const float* __restrict__ A, const float* __restrict__ B,
              const float* __restrict__ bias, const float* __restrict__ res,
              float* __restrict__ out,
              int lda, int ldb, int ldo, int K, float scale,
              size_t sA, size_t sB, size_t sO, size_t sR) {
    constexpr int STG = 16384;           // one operand-stage: 128 rows x 128B
    extern __shared__ char smem[];       // [A0 A1 B0 B1] = 64KB
    const uint32_t sb = smem_u32(smem);
    const uint32_t sbB = sb + 2 * STG;

    const int bz = blockIdx.z;
    A += (size_t)bz * sA;
    B += (size_t)bz * sB;
    out += (size_t)bz * sO;
    if (RES) res += (size_t)bz * sR;

    const int m0 = blockIdx.y * 128;
    const int n0 = blockIdx.x * 128;
    const int tid = threadIdx.x;
    const int lane = tid & 31;
    const int wid = tid >> 5;
    const int wm = wid & 1;              // 2 x 64 rows
    const int wn = wid >> 1;             // 4 x 32 cols

    // ---- cp.async geometry: thread covers 4 chunks (16B) per operand ----
    const int r0 = tid >> 3;             // rows 0..31 (+32*it)
    const int cb = tid & 7;              // 16B chunk in row
    const float* gA = A + (size_t)(m0 + r0) * lda + cb * 4;
    const float* gB = B + (size_t)(n0 + r0) * ldb + cb * 4;
    uint32_t soff[4];
    #pragma unroll
    for (int it = 0; it < 4; it++) {
        const int row = r0 + 32 * it;
        soff[it] = (uint32_t)row * 128u + (uint32_t)((cb ^ (row & 7)) << 4);
    }

    // ---- ldmatrix geometry ----
    const int aRow = wm * 64 + (lane & 15);
    const uint32_t aRowOff = (uint32_t)aRow * 128u;
    const int aCk = lane >> 4;           // +0/+1 chunk
    const int aXr = aRow & 7;
    const int bRow = wn * 32 + (lane & 7) + ((lane >> 4) << 3);
    const uint32_t bRowOff = (uint32_t)bRow * 128u;
    const int bCk = (lane >> 3) & 1;
    const int bXr = bRow & 7;

    float acc[4][4][4];
    #pragma unroll
    for (int mi = 0; mi < 4; mi++)
        #pragma unroll
        for (int ni = 0; ni < 4; ni++)
            #pragma unroll
            for (int r = 0; r < 4; r++) acc[mi][ni][r] = 0.f;

    auto load_tile = [&](int i, int s) {
        const float* ga = gA + (size_t)i * 32;
        const float* gb_ = gB + (size_t)i * 32;
        const uint32_t sa = sb + s * STG;
        const uint32_t sbb = sbB + s * STG;
        #pragma unroll
        for (int it = 0; it < 4; it++)
            asm volatile("cp.async.cg.shared.global [%0], [%1], 16;"
                :: "r"(sa + soff[it]), "l"(ga + (size_t)(32 * it) * lda) : "memory");
        #pragma unroll
        for (int it = 0; it < 4; it++)
            asm volatile("cp.async.cg.shared.global [%0], [%1], 16;"
                :: "r"(sbb + soff[it]), "l"(gb_ + (size_t)(32 * it) * ldb) : "memory");
    };

    const int NT = K / 32;
    load_tile(0, 0);
    asm volatile("cp.async.commit_group;" ::: "memory");

    for (int i = 0; i < NT; i++) {
        if (i + 1 < NT) load_tile(i + 1, (i + 1) & 1);
        asm volatile("cp.async.commit_group;" ::: "memory");
        asm volatile("cp.async.wait_group %0;" :: "n"(1) : "memory");
        __syncthreads();

        const uint32_t saS = sb + (i & 1) * STG;
        const uint32_t sbS = sbB + (i & 1) * STG;
        #pragma unroll
        for (int kk = 0; kk < 32; kk += 8) {
            const int ck = kk >> 2;
            uint32_t af[4][4], bf[4][2];
            #pragma unroll
            for (int mi = 0; mi < 4; mi++)
                ldsm_x4(af[mi][0], af[mi][1], af[mi][2], af[mi][3],
                        saS + aRowOff + (uint32_t)(mi * 2048)
                            + (uint32_t)((((ck + aCk) ^ aXr)) << 4));
            #pragma unroll
            for (int np = 0; np < 2; np++)
                ldsm_x4(bf[2 * np][0], bf[2 * np][1], bf[2 * np + 1][0], bf[2 * np + 1][1],
                        sbS + bRowOff + (uint32_t)(np * 2048)
                            + (uint32_t)((((ck + bCk) ^ bXr)) << 4));
            #pragma unroll
            for (int mi = 0; mi < 4; mi++)
                #pragma unroll
                for (int ni = 0; ni < 4; ni++)
                    mma_tf32(acc[mi][ni], af[mi], bf[ni]);
        }
        __syncthreads();
    }

    // ---- epilogue ----
    #pragma unroll
    for (int mi = 0; mi < 4; mi++) {
        const int rbase = m0 + wm * 64 + mi * 16 + (lane >> 2);
        #pragma unroll
        for (int ni = 0; ni < 4; ni++) {
            const int cc = n0 + wn * 32 + ni * 8 + 2 * (lane & 3);
            #pragma unroll
            for (int half = 0; half < 2; half++) {
                const int r = rbase + half * 8;
                float2 v;
                v.x = acc[mi][ni][half * 2 + 0] * scale;
                v.y = acc[mi][ni][half * 2 + 1] * scale;
                if (BIAS == 1) { v.x += bias[cc]; v.y += bias[cc + 1]; }
                else if (BIAS == 2) { const float bm = bias[r]; v.x += bm; v.y += bm; }
                if (RES) {
                    float2 rr = *(const float2*)&res[(size_t)r * ldo + cc];
                    v.x += rr.x; v.y += rr.y;
                }
                *(float2*)&out[(size_t)r * ldo + cc] = v;
            }
        }
    }
}

// ---------------- row softmax (in place) ----------------
__global__ __launch_bounds__(256)
void softmax_kernel(float* __restrict__ s) {
    const size_t row = blockIdx.x;
    float4* p4 = (float4*)(s + row * HWT);
    __shared__ float buf[HWT];
    __shared__ float red[32];
    float4* b4 = (float4*)buf;
    const int tid = threadIdx.x;
    const int wid = tid >> 5, lid = tid & 31;

    float mx = -1e30f;
    for (int i = tid; i < HWT / 4; i += 256) {
        float4 v = p4[i];
        b4[i] = v;
        mx = fmaxf(mx, fmaxf(fmaxf(v.x, v.y), fmaxf(v.z, v.w)));
    }
    #pragma unroll
    for (int o = 16; o > 0; o >>= 1) mx = fmaxf(mx, __shfl_xor_sync(~0u, mx, o));
    if (lid == 0) red[wid] = mx;
    __syncthreads();
    if (tid == 0) {
        float m2 = red[0];
        for (int i = 1; i < 8; i++) m2 = fmaxf(m2, red[i]);
        red[0] = m2;
    }
    __syncthreads();
    const float rowmax = red[0];
    __syncthreads();

    float sum = 0.f;
    for (int i = tid; i < HWT / 4; i += 256) {
        float4 v = b4[i];
        v.x = __expf(v.x - rowmax); v.y = __expf(v.y - rowmax);
        v.z = __expf(v.z - rowmax); v.w = __expf(v.w - rowmax);
        sum += v.x + v.y + v.z + v.w;
        b4[i] = v;
    }
    #pragma unroll
    for (int o = 16; o > 0; o >>= 1) sum += __shfl_xor_sync(~0u, sum, o);
    if (lid == 0) red[wid] = sum;
    __syncthreads();
    if (tid == 0) {
        float t = 0.f;
        for (int i = 0; i < 8; i++) t += red[i];
        red[0] = t;
    }
    __syncthreads();
    const float inv = 1.f / red[0];
    for (int i = tid; i < HWT / 4; i += 256) {
        float4 v = b4[i];
        v.x *= inv; v.y *= inv; v.z *= inv; v.w *= inv;
        p4[i] = v;
    }
}

// ---------------- launch ----------------
extern "C" void kernel_launch(void* const* d_in, const int* in_sizes, int n_in,
                              void* d_out, int out_size) {
    const float* x    = (const float*)d_in[0];
    const float* gn_w = (const float*)d_in[1];
    const float* gn_b = (const float*)d_in[2];
    const float* q_w  = (const float*)d_in[3];
    const float* q_b  = (const float*)d_in[4];
    const float* k_w  = (const float*)d_in[5];
    const float* k_b  = (const float*)d_in[6];
    const float* v_w  = (const float*)d_in[7];
    const float* v_b  = (const float*)d_in[8];
    const float* p_w  = (const float*)d_in[9];
    const float* p_b  = (const float*)d_in[10];
    float* out = (float*)d_out;

    float *h, *q, *k, *v, *o, *s;
    float2* st;
    cudaGetSymbolAddress((void**)&h, g_h);
    cudaGetSymbolAddress((void**)&q, g_q);
    cudaGetSymbolAddress((void**)&k, g_k);
    cudaGetSymbolAddress((void**)&v, g_v);
    cudaGetSymbolAddress((void**)&o, g_o);
    cudaGetSymbolAddress((void**)&s, g_s);
    cudaGetSymbolAddress((void**)&st, g_stats);

    const int SMEM_T = 65536;
    cudaFuncSetAttribute(mma_gemm<0, false>, cudaFuncAttributeMaxDynamicSharedMemorySize, SMEM_T);
    cudaFuncSetAttribute(mma_gemm<1, false>, cudaFuncAttributeMaxDynamicSharedMemorySize, SMEM_T);
    cudaFuncSetAttribute(mma_gemm<2, false>, cudaFuncAttributeMaxDynamicSharedMemorySize, SMEM_T);
    cudaFuncSetAttribute(mma_gemm<2, true>,  cudaFuncAttributeMaxDynamicSharedMemorySize, SMEM_T);

    const size_t TOK = (size_t)HWT * CCH;
    const size_t SS  = (size_t)HWT * HWT;
    const size_t CHW = (size_t)CCH * HWT;
    const float att_scale = 0.04419417382415922f; // 1/sqrt(512)

    // 1. GroupNorm stats + apply/transpose -> h token-major
    gn_stats<<<BATCH * NGROUPS, 512>>>(x, st);
    gn_apply_t<<<dim3(HWT / 32, CCH / 32, BATCH), dim3(32, 8)>>>(x, gn_w, gn_b, st, h);

    // 2. q, k token-major: M=HW, N=C, K=C
    dim3 gq(CCH / 128, HWT / 128, BATCH);
    mma_gemm<1, false><<<gq, 256, SMEM_T>>>(h, q_w, q_b, nullptr, q,
        CCH, CCH, CCH, CCH, 1.f, TOK, 0, TOK, 0);
    mma_gemm<1, false><<<gq, 256, SMEM_T>>>(h, k_w, k_b, nullptr, k,
        CCH, CCH, CCH, CCH, 1.f, TOK, 0, TOK, 0);

    // 3. v channel-major: M=C, N=HW, K=C  (A=v_w, B=h)
    dim3 gv(HWT / 128, CCH / 128, BATCH);
    mma_gemm<2, false><<<gv, 256, SMEM_T>>>(v_w, h, v_b, nullptr, v,
        CCH, CCH, HWT, CCH, 1.f, 0, TOK, TOK, 0);

    // 4. scores = scale * Q @ K^T : M=N=HW, K=C
    dim3 gs(HWT / 128, HWT / 128, BATCH);
    mma_gemm<0, false><<<gs, 256, SMEM_T>>>(q, k, nullptr, nullptr, s,
        CCH, CCH, HWT, CCH, att_scale, TOK, TOK, SS, 0);

    // 5. softmax rows
    softmax_kernel<<<BATCH * HWT, 256>>>(s);

    // 6. o = attn @ V : M=HW, N=C, K=HW  (B = v channel-major, k=t contiguous)
    dim3 ga(CCH / 128, HWT / 128, BATCH);
    mma_gemm<0, false><<<ga, 256, SMEM_T>>>(s, v, nullptr, nullptr, o,
        HWT, HWT, CCH, HWT, 1.f, SS, TOK, TOK, 0);

    // 7. out = x + P @ o^T (channel-major): M=C, N=HW, K=C
    dim3 gp(HWT / 128, CCH / 128, BATCH);
    mma_gemm<2, true><<<gp, 256, SMEM_T>>>(p_w, o, p_b, x, out,
        CCH, CCH, HWT, CCH, 1.f, 0, TOK, CHW, CHW);
}

// round 5
// speedup vs baseline: 7.2469x; 1.7266x over previous
#include <cuda_runtime.h>
#include <cuda_fp16.h>
#include <math.h>
#include <stdint.h>

#define CCH 512
#define HWT 4096
#define BATCH 2
#define NGROUPS 32
#define CPG 16

// ---------------- scratch (allocation-free) ----------------
__device__ __half  g_h[(size_t)BATCH * HWT * CCH];   // normalized, token-major
__device__ __half  g_q[(size_t)BATCH * HWT * CCH];
__device__ __half  g_k[(size_t)BATCH * HWT * CCH];
__device__ __half  g_v[(size_t)BATCH * CCH * HWT];   // channel-major
__device__ __half  g_o[(size_t)BATCH * HWT * CCH];   // attn out, token-major
__device__ __half  g_s[(size_t)BATCH * HWT * HWT];   // scores / probs
__device__ __half  g_w[4 * CCH * CCH];               // q_w, k_w, v_w, p_w fp16
__device__ float2  g_stats[BATCH * NGROUPS];

// ---------------- helpers ----------------
__device__ __forceinline__ uint32_t smem_u32(const void* p) {
    uint32_t a;
    asm("{ .reg .u64 t; cvta.to.shared.u64 t, %1; cvt.u32.u64 %0, t; }" : "=r"(a) : "l"(p));
    return a;
}
__device__ __forceinline__ void ldsm_x4(uint32_t& r0, uint32_t& r1, uint32_t& r2, uint32_t& r3,
                                        uint32_t addr) {
    asm volatile("ldmatrix.sync.aligned.m8n8.x4.shared.b16 {%0,%1,%2,%3}, [%4];"
                 : "=r"(r0), "=r"(r1), "=r"(r2), "=r"(r3) : "r"(addr));
}
__device__ __forceinline__ void mma_f16(float* c, const uint32_t* a, const uint32_t* b) {
    asm("mma.sync.aligned.m16n8k16.row.col.f32.f16.f16.f32 "
        "{%0,%1,%2,%3}, {%4,%5,%6,%7}, {%8,%9}, {%0,%1,%2,%3};"
        : "+f"(c[0]), "+f"(c[1]), "+f"(c[2]), "+f"(c[3])
        : "r"(a[0]), "r"(a[1]), "r"(a[2]), "r"(a[3]), "r"(b[0]), "r"(b[1]));
}

// ---------------- fp32 -> fp16 weight convert ----------------
__global__ void w2h_kernel(const float* __restrict__ s0, const float* __restrict__ s1,
                           const float* __restrict__ s2, const float* __restrict__ s3,
                           __half* __restrict__ dst) {
    const int i = blockIdx.x * blockDim.x + threadIdx.x;
    const int N = CCH * CCH;
    dst[i]         = __float2half_rn(s0[i]);
    dst[i + N]     = __float2half_rn(s1[i]);
    dst[i + 2 * N] = __float2half_rn(s2[i]);
    dst[i + 3 * N] = __float2half_rn(s3[i]);
}

// ---------------- GroupNorm stats ----------------
__global__ void gn_stats(const float* __restrict__ x, float2* __restrict__ st) {
    const int bg = blockIdx.x;
    const size_t base = (size_t)bg * CPG * HWT;
    const float4* xp = (const float4*)(x + base);
    const int N4 = CPG * HWT / 4;

    float s = 0.f, ss = 0.f;
    for (int i = threadIdx.x; i < N4; i += blockDim.x) {
        float4 v = xp[i];
        s  += v.x + v.y + v.z + v.w;
        ss += v.x * v.x + v.y * v.y + v.z * v.z + v.w * v.w;
    }
    __shared__ float rs[32], rss[32];
    #pragma unroll
    for (int o = 16; o > 0; o >>= 1) {
        s  += __shfl_xor_sync(~0u, s,  o);
        ss += __shfl_xor_sync(~0u, ss, o);
    }
    const int wid = threadIdx.x >> 5, lid = threadIdx.x & 31;
    if (lid == 0) { rs[wid] = s; rss[wid] = ss; }
    __syncthreads();
    if (threadIdx.x == 0) {
        const int nw = blockDim.x >> 5;
        float ts = 0.f, tss = 0.f;
        for (int i = 0; i < nw; i++) { ts += rs[i]; tss += rss[i]; }
        const float invN = 1.f / (float)(CPG * HWT);
        const float mean = ts * invN;
        const float var  = fmaxf(tss * invN - mean * mean, 0.f);
        st[bg] = make_float2(mean, rsqrtf(var + 1e-6f));
    }
}

// ---------------- GN apply + transpose -> token-major fp16 h ----------------
__global__ void gn_apply_t(const float* __restrict__ x,
                           const float* __restrict__ gw, const float* __restrict__ gb,
                           const float2* __restrict__ st, __half* __restrict__ ht) {
    __shared__ float tile[32][33];
    const int b = blockIdx.z;
    const int c0 = blockIdx.y * 32, t0 = blockIdx.x * 32;
    const float* xp = x + (size_t)b * CCH * HWT;
    __half* hp = ht + (size_t)b * HWT * CCH;

    #pragma unroll
    for (int j = threadIdx.y; j < 32; j += 8)
        tile[j][threadIdx.x] = xp[(size_t)(c0 + j) * HWT + t0 + threadIdx.x];
    __syncthreads();

    const int c = c0 + threadIdx.x;
    const float2 mv = st[b * NGROUPS + (c >> 4)];
    const float a  = mv.y * gw[c];
    const float bo = gb[c] - mv.x * a;
    #pragma unroll
    for (int j = threadIdx.y; j < 32; j += 8)
        hp[(size_t)(t0 + j) * CCH + c] = __float2half_rn(tile[threadIdx.x][j] * a + bo);
}

// ---------------- fp16 HMMA GEMM (3-stage cp.async, ldmatrix) ----------------
// out[m][n] = scale * sum_k A[m][k]*B[n][k] (+bias)(+res); A,B fp16 k-contiguous.
// BIAS: 0 none, 1 per-n, 2 per-m.  RES (float out only) adds res[m*ldo+n].
template<int BIAS, bool RES, typename OutT>
__global__ __launch_bounds__(256, 2)
void mma_gemm(const __half* __restrict__ A, const __half* __restrict__ B,
              const float* __restrict__ bias, const float* __restrict__ res,
              OutT* __restrict__ out,
              int lda, int ldb, int ldo, int K, float scale,
              size_t sA, size_t sB, size_t sO, size_t sR) {
    constexpr int STG = 16384;           // one operand-stage: 128 rows x 128B (64 fp16)
    constexpr int NSTG = 3;
    extern __shared__ char smem[];       // [A0 A1 A2 | B0 B1 B2] = 96KB
    const uint32_t sb = smem_u32(smem);
    const uint32_t sbB = sb + NSTG * STG;

    const int bz = blockIdx.z;
    A += (size_t)bz * sA;
    B += (size_t)bz * sB;
    out += (size_t)bz * sO;
    if (RES) res += (size_t)bz * sR;

    const int m0 = blockIdx.y * 128;
    const int n0 = blockIdx.x * 128;
    const int tid = threadIdx.x;
    const int lane = tid & 31;
    const int wid = tid >> 5;
    const int wm = wid & 1;              // 2 x 64 rows
    const int wn = wid >> 1;             // 4 x 32 cols

    // ---- cp.async geometry: 4 chunks (16B) per operand per thread ----
    const int r0 = tid >> 3;             // rows 0..31 (+32*it)
    const int cb = tid & 7;              // 16B chunk in row (8 fp16)
    const __half* gA = A + (size_t)(m0 + r0) * lda + cb * 8;
    const __half* gB = B + (size_t)(n0 + r0) * ldb + cb * 8;
    uint32_t soff[4];
    #pragma unroll
    for (int it = 0; it < 4; it++) {
        const int row = r0 + 32 * it;
        soff[it] = (uint32_t)row * 128u + (uint32_t)((cb ^ (row & 7)) << 4);
    }

    // ---- ldmatrix geometry ----
    const int aRowB = wm * 64 + (lane & 15);           // + mi*16
    const int aCk = (lane >> 4) & 1;
    const int aXr = aRowB & 7;
    const int bRowB = wn * 32 + (lane & 7) + (((lane >> 4) & 1) << 3);  // + ni2*16
    const int bCk = (lane >> 3) & 1;
    const int bXr = lane & 7;

    float acc[4][4][4];
    #pragma unroll
    for (int mi = 0; mi < 4; mi++)
        #pragma unroll
        for (int ni = 0; ni < 4; ni++)
            #pragma unroll
            for (int r = 0; r < 4; r++) acc[mi][ni][r] = 0.f;

    auto load_tile = [&](int i, int s) {
        const __half* ga = gA + (size_t)i * 64;
        const __half* gb_ = gB + (size_t)i * 64;
        const uint32_t sa = sb + s * STG;
        const uint32_t sbb = sbB + s * STG;
        #pragma unroll
        for (int it = 0; it < 4; it++)
            asm volatile("cp.async.cg.shared.global [%0], [%1], 16;"
                :: "r"(sa + soff[it]), "l"(ga + (size_t)(32 * it) * lda) : "memory");
        #pragma unroll
        for (int it = 0; it < 4; it++)
            asm volatile("cp.async.cg.shared.global [%0], [%1], 16;"
                :: "r"(sbb + soff[it]), "l"(gb_ + (size_t)(32 * it) * ldb) : "memory");
    };

    const int NT = K / 64;
    load_tile(0, 0);
    asm volatile("cp.async.commit_group;" ::: "memory");
    load_tile(1, 1);
    asm volatile("cp.async.commit_group;" ::: "memory");

    int stage = 0;
    for (int i = 0; i < NT; i++) {
        asm volatile("cp.async.wait_group %0;" :: "n"(1) : "memory");
        __syncthreads();
        if (i + 2 < NT) {
            int s2 = stage + 2; if (s2 >= NSTG) s2 -= NSTG;
            load_tile(i + 2, s2);
        }
        asm volatile("cp.async.commit_group;" ::: "memory");

        const uint32_t saS = sb + stage * STG;
        const uint32_t sbS = sbB + stage * STG;
        #pragma unroll
        for (int t = 0; t < 4; t++) {               // 4 k16 steps per BK=64
            uint32_t af[4][4], bf[4][2];
            #pragma unroll
            for (int mi = 0; mi < 4; mi++)
                ldsm_x4(af[mi][0], af[mi][1], af[mi][2], af[mi][3],
                        saS + (uint32_t)(aRowB + mi * 16) * 128u
                            + (uint32_t)(((2 * t + aCk) ^ aXr) << 4));
            #pragma unroll
            for (int ni2 = 0; ni2 < 2; ni2++)
                ldsm_x4(bf[2 * ni2][0], bf[2 * ni2][1], bf[2 * ni2 + 1][0], bf[2 * ni2 + 1][1],
                        sbS + (uint32_t)(bRowB + ni2 * 16) * 128u
                            + (uint32_t)(((2 * t + bCk) ^ bXr) << 4));
            #pragma unroll
            for (int mi = 0; mi < 4; mi++)
                #pragma unroll
                for (int ni = 0; ni < 4; ni++)
                    mma_f16(acc[mi][ni], af[mi], bf[ni]);
        }
        stage++; if (stage >= NSTG) stage -= NSTG;
    }

    // ---- epilogue ----
    #pragma unroll
    for (int mi = 0; mi < 4; mi++) {
        const int rbase = m0 + wm * 64 + mi * 16 + (lane >> 2);
        #pragma unroll
        for (int ni = 0; ni < 4; ni++) {
            const int cc = n0 + wn * 32 + ni * 8 + 2 * (lane & 3);
            #pragma unroll
            for (int hf = 0; hf < 2; hf++) {
                const int r = rbase + hf * 8;
                float vx = acc[mi][ni][hf * 2 + 0] * scale;
                float vy = acc[mi][ni][hf * 2 + 1] * scale;
                if (BIAS == 1) { vx += bias[cc]; vy += bias[cc + 1]; }
                else if (BIAS == 2) { const float bm = bias[r]; vx += bm; vy += bm; }
                if (sizeof(OutT) == 2) {
                    *(__half2*)((__half*)out + (size_t)r * ldo + cc) =
                        __floats2half2_rn(vx, vy);
                } else {
                    if (RES) {
                        float2 rr = *(const float2*)&res[(size_t)r * ldo + cc];
                        vx += rr.x; vy += rr.y;
                    }
                    float2 v; v.x = vx; v.y = vy;
                    *(float2*)((float*)out + (size_t)r * ldo + cc) = v;
                }
            }
        }
    }
}

// ---------------- fp16 row softmax (in place) ----------------
__global__ __launch_bounds__(256)
void softmax_kernel(__half* __restrict__ s) {
    const size_t row = blockIdx.x;
    __half2* p2 = (__half2*)(s + row * HWT);
    __shared__ float buf[HWT];
    __shared__ float red[32];
    float2* b2 = (float2*)buf;
    const int tid = threadIdx.x;
    const int wid = tid >> 5, lid = tid & 31;

    float mx = -1e30f;
    for (int i = tid; i < HWT / 2; i += 256) {
        float2 v = __half22float2(p2[i]);
        b2[i] = v;
        mx = fmaxf(mx, fmaxf(v.x, v.y));
    }
    #pragma unroll
    for (int o = 16; o > 0; o >>= 1) mx = fmaxf(mx, __shfl_xor_sync(~0u, mx, o));
    if (lid == 0) red[wid] = mx;
    __syncthreads();
    if (tid == 0) {
        float m2 = red[0];
        for (int i = 1; i < 8; i++) m2 = fmaxf(m2, red[i]);
        red[0] = m2;
    }
    __syncthreads();
    const float rowmax = red[0];
    __syncthreads();

    float sum = 0.f;
    for (int i = tid; i < HWT / 2; i += 256) {
        float2 v = b2[i];
        v.x = __expf(v.x - rowmax); v.y = __expf(v.y - rowmax);
        sum += v.x + v.y;
        b2[i] = v;
    }
    #pragma unroll
    for (int o = 16; o > 0; o >>= 1) sum += __shfl_xor_sync(~0u, sum, o);
    if (lid == 0) red[wid] = sum;
    __syncthreads();
    if (tid == 0) {
        float t = 0.f;
        for (int i = 0; i < 8; i++) t += red[i];
        red[0] = t;
    }
    __syncthreads();
    const float inv = 1.f / red[0];
    for (int i = tid; i < HWT / 2; i += 256) {
        float2 v = b2[i];
        p2[i] = __floats2half2_rn(v.x * inv, v.y * inv);
    }
}

// ---------------- launch ----------------
extern "C" void kernel_launch(void* const* d_in, const int* in_sizes, int n_in,
                              void* d_out, int out_size) {
    const float* x    = (const float*)d_in[0];
    const float* gn_w = (const float*)d_in[1];
    const float* gn_b = (const float*)d_in[2];
    const float* q_w  = (const float*)d_in[3];
    const float* q_b  = (const float*)d_in[4];
    const float* k_w  = (const float*)d_in[5];
    const float* k_b  = (const float*)d_in[6];
    const float* v_w  = (const float*)d_in[7];
    const float* v_b  = (const float*)d_in[8];
    const float* p_w  = (const float*)d_in[9];
    const float* p_b  = (const float*)d_in[10];
    float* out = (float*)d_out;

    __half *h, *q, *k, *v, *o, *s, *w;
    float2* st;
    cudaGetSymbolAddress((void**)&h, g_h);
    cudaGetSymbolAddress((void**)&q, g_q);
    cudaGetSymbolAddress((void**)&k, g_k);
    cudaGetSymbolAddress((void**)&v, g_v);
    cudaGetSymbolAddress((void**)&o, g_o);
    cudaGetSymbolAddress((void**)&s, g_s);
    cudaGetSymbolAddress((void**)&w, g_w);
    cudaGetSymbolAddress((void**)&st, g_stats);

    const int SMEM_T = 3 * 2 * 16384;    // 98304
    cudaFuncSetAttribute(mma_gemm<0, false, __half>, cudaFuncAttributeMaxDynamicSharedMemorySize, SMEM_T);
    cudaFuncSetAttribute(mma_gemm<1, false, __half>, cudaFuncAttributeMaxDynamicSharedMemorySize, SMEM_T);
    cudaFuncSetAttribute(mma_gemm<2, false, __half>, cudaFuncAttributeMaxDynamicSharedMemorySize, SMEM_T);
    cudaFuncSetAttribute(mma_gemm<2, true, float>,   cudaFuncAttributeMaxDynamicSharedMemorySize, SMEM_T);

    const size_t TOK = (size_t)HWT * CCH;
    const size_t SS  = (size_t)HWT * HWT;
    const size_t CHW = (size_t)CCH * HWT;
    const int WN = CCH * CCH;
    const float att_scale = 0.04419417382415922f; // 1/sqrt(512)

    // 0. weights -> fp16
    w2h_kernel<<<WN / 256, 256>>>(q_w, k_w, v_w, p_w, w);
    __half* qw = w;
    __half* kw = w + WN;
    __half* vw = w + 2 * WN;
    __half* pw = w + 3 * WN;

    // 1. GroupNorm stats + apply/transpose -> h token-major fp16
    gn_stats<<<BATCH * NGROUPS, 512>>>(x, st);
    gn_apply_t<<<dim3(HWT / 32, CCH / 32, BATCH), dim3(32, 8)>>>(x, gn_w, gn_b, st, h);

    // 2. q, k token-major: M=HW, N=C, K=C
    dim3 gq(CCH / 128, HWT / 128, BATCH);
    mma_gemm<1, false, __half><<<gq, 256, SMEM_T>>>(h, qw, q_b, nullptr, q,
        CCH, CCH, CCH, CCH, 1.f, TOK, 0, TOK, 0);
    mma_gemm<1, false, __half><<<gq, 256, SMEM_T>>>(h, kw, k_b, nullptr, k,
        CCH, CCH, CCH, CCH, 1.f, TOK, 0, TOK, 0);

    // 3. v channel-major: M=C, N=HW, K=C  (A=v_w, B=h)
    dim3 gv(HWT / 128, CCH / 128, BATCH);
    mma_gemm<2, false, __half><<<gv, 256, SMEM_T>>>(vw, h, v_b, nullptr, v,
        CCH, CCH, HWT, CCH, 1.f, 0, TOK, TOK, 0);

    // 4. scores = scale * Q @ K^T : M=N=HW, K=C
    dim3 gs(HWT / 128, HWT / 128, BATCH);
    mma_gemm<0, false, __half><<<gs, 256, SMEM_T>>>(q, k, nullptr, nullptr, s,
        CCH, CCH, HWT, CCH, att_scale, TOK, TOK, SS, 0);

    // 5. softmax rows
    softmax_kernel<<<BATCH * HWT, 256>>>(s);

    // 6. o = attn @ V : M=HW, N=C, K=HW (B = v channel-major)
    dim3 ga(CCH / 128, HWT / 128, BATCH);
    mma_gemm<0, false, __half><<<ga, 256, SMEM_T>>>(s, v, nullptr, nullptr, o,
        HWT, HWT, CCH, HWT, 1.f, SS, TOK, TOK, 0);

    // 7. out = x + P @ o^T (channel-major): M=C, N=HW, K=C
    dim3 gp(HWT / 128, CCH / 128, BATCH);
    mma_gemm<2, true, float><<<gp, 256, SMEM_T>>>(pw, o, p_b, x, out,
        CCH, CCH, HWT, CCH, 1.f, 0, TOK, CHW, CHW);
}